// round 1
// baseline (speedup 1.0000x reference)
#include <cuda_runtime.h>
#include <math.h>

// Problem constants
#define Bq 8
#define Sq 1024
#define Eq 512
#define Hq 8
#define Dq 64
#define BSq (Bq * Sq)

// Scratch (allocation-free: __device__ globals)
__device__ float g_q[BSq * Eq];   // q @ Wk^T + bk
__device__ float g_k[BSq * Eq];   // k @ Wk^T + bk
__device__ float g_v[BSq * Eq];   // v @ Wv^T + bv
__device__ float g_a[BSq * Eq];   // attention output (pre output-proj)

// ---------------------------------------------------------------------------
// GEMM: C[m,n] = sum_k A[m,k] * W[n,k] + bias[n]   (A:[8192,512], W:[512,512])
// 128x128 tile, BK=8, 256 threads, 8x8 microtile.
// out_sel: 0->g_q, 1->g_k, 2->g_v, 3->Cp.  Ap==nullptr -> read from g_a.
// ---------------------------------------------------------------------------
__global__ __launch_bounds__(256) void gemm_nt(const float* __restrict__ Ap,
                                               const float* __restrict__ W,
                                               const float* __restrict__ bias,
                                               float* __restrict__ Cp,
                                               int out_sel)
{
    const float* A = Ap ? Ap : g_a;
    float* C = (out_sel == 0) ? g_q : (out_sel == 1) ? g_k : (out_sel == 2) ? g_v : Cp;

    __shared__ float As[8][128];
    __shared__ float Ws[8][128];

    const int bm = blockIdx.y * 128;
    const int bn = blockIdx.x * 128;
    const int tid = threadIdx.x;
    const int lr = tid >> 1;          // 0..127: row in tile for loading
    const int lc = (tid & 1) * 4;     // 0 or 4: k-offset (float4)
    const int tm = (tid >> 4) * 8;    // microtile row base
    const int tn = (tid & 15) * 8;    // microtile col base

    float acc[8][8];
#pragma unroll
    for (int y = 0; y < 8; y++)
#pragma unroll
        for (int x = 0; x < 8; x++) acc[y][x] = 0.f;

    const float* Arow = A + (size_t)(bm + lr) * Eq + lc;
    const float* Wrow = W + (size_t)(bn + lr) * Eq + lc;

    for (int k0 = 0; k0 < Eq; k0 += 8) {
        float4 av = *(const float4*)(Arow + k0);
        float4 wv = *(const float4*)(Wrow + k0);
        __syncthreads();
        As[lc + 0][lr] = av.x; As[lc + 1][lr] = av.y;
        As[lc + 2][lr] = av.z; As[lc + 3][lr] = av.w;
        Ws[lc + 0][lr] = wv.x; Ws[lc + 1][lr] = wv.y;
        Ws[lc + 2][lr] = wv.z; Ws[lc + 3][lr] = wv.w;
        __syncthreads();
#pragma unroll
        for (int kk = 0; kk < 8; kk++) {
            float ar[8], br[8];
#pragma unroll
            for (int x = 0; x < 8; x++) { ar[x] = As[kk][tm + x]; br[x] = Ws[kk][tn + x]; }
#pragma unroll
            for (int y = 0; y < 8; y++)
#pragma unroll
                for (int x = 0; x < 8; x++) acc[y][x] += ar[y] * br[x];
        }
    }

#pragma unroll
    for (int y = 0; y < 8; y++) {
        float* crow = C + (size_t)(bm + tm + y) * Eq + bn + tn;
#pragma unroll
        for (int x = 0; x < 8; x++) crow[x] = acc[y][x] + bias[bn + tn + x];
    }
}

// ---------------------------------------------------------------------------
// Attention with distance-decay (FoLiBi). One warp per query row, 8 rows/block.
// Two passes over K (tiles of 32 rows in shared):
//   A: online (max, sumexp) of masked scores -> m1, l1
//   B: recompute scores; sm = softmax1; warp-scan cumsum; suffix = 1 - cumsum;
//      dist = sqrt(clip(suffix*(i-j),0)); eff = clip(exp(gamma*dist),1e-5,1e5);
//      online softmax-2 of s*eff fused with V accumulation.
// Row i==0 output forced to zero (reference zero-pads first query row).
// ---------------------------------------------------------------------------
__device__ __forceinline__ float wmax(float v) {
#pragma unroll
    for (int o = 16; o > 0; o >>= 1) v = fmaxf(v, __shfl_xor_sync(0xffffffffu, v, o));
    return v;
}
__device__ __forceinline__ float wsum(float v) {
#pragma unroll
    for (int o = 16; o > 0; o >>= 1) v += __shfl_xor_sync(0xffffffffu, v, o);
    return v;
}

__global__ __launch_bounds__(256) void attn_kernel(const float* __restrict__ gammas)
{
    __shared__ float Ks[32][65];   // padded: conflict-free per-d column reads
    __shared__ float Vs[32][64];   // per-j row reads are naturally conflict-free

    const int b = blockIdx.z;
    const int h = blockIdx.y;
    const int r0 = blockIdx.x * 8;
    const int warp = threadIdx.x >> 5;
    const int lane = threadIdx.x & 31;
    const int i = r0 + warp;

    // gamma = -softplus(gammas[h])  (numerically stable softplus)
    const float gv = gammas[h];
    const float gamma = -(fmaxf(gv, 0.f) + log1pf(__expf(-fabsf(gv))));

    // q row in registers (scale 1/sqrt(64) folded in)
    float qreg[Dq];
    const float* qrow = g_q + (size_t)(b * Sq + i) * Eq + h * Dq;
#pragma unroll
    for (int d = 0; d < Dq; d++) qreg[d] = qrow[d] * 0.125f;

    const int ntiles = (r0 + 8 + 31) >> 5;   // covers j in [0, r0+7]
    const float NEGINF = -INFINITY;

    // ---------------- Pass A: m1, l1 ----------------
    float m1 = NEGINF, l1 = 0.f;
    for (int t = 0; t < ntiles; t++) {
        const int jt = t << 5;
        __syncthreads();
        for (int idx = threadIdx.x; idx < 32 * 16; idx += 256) {
            const int row = idx >> 4, c4 = (idx & 15) << 2;
            float4 kv = *(const float4*)(g_k + (size_t)(b * Sq + jt + row) * Eq + h * Dq + c4);
            Ks[row][c4 + 0] = kv.x; Ks[row][c4 + 1] = kv.y;
            Ks[row][c4 + 2] = kv.z; Ks[row][c4 + 3] = kv.w;
        }
        __syncthreads();
        const int j = jt + lane;
        float s = 0.f;
#pragma unroll
        for (int d = 0; d < Dq; d++) s += qreg[d] * Ks[lane][d];
        s = (j <= i) ? s : NEGINF;
        const float mn = fmaxf(m1, wmax(s));
        l1 = l1 * __expf(m1 - mn) + wsum(__expf(s - mn));
        m1 = mn;
    }
    const float invl1 = 1.f / l1;

    // ---------------- Pass B: decay + softmax2 + PV ----------------
    float m2 = NEGINF, l2 = 0.f, Crun = 0.f, o0 = 0.f, o1 = 0.f;
    for (int t = 0; t < ntiles; t++) {
        const int jt = t << 5;
        __syncthreads();
        for (int idx = threadIdx.x; idx < 32 * 16; idx += 256) {
            const int row = idx >> 4, c4 = (idx & 15) << 2;
            const size_t goff = (size_t)(b * Sq + jt + row) * Eq + h * Dq + c4;
            float4 kv = *(const float4*)(g_k + goff);
            Ks[row][c4 + 0] = kv.x; Ks[row][c4 + 1] = kv.y;
            Ks[row][c4 + 2] = kv.z; Ks[row][c4 + 3] = kv.w;
            *(float4*)&Vs[row][c4] = *(const float4*)(g_v + goff);
        }
        __syncthreads();
        const int j = jt + lane;
        const bool valid = (j <= i);
        float s = 0.f;
#pragma unroll
        for (int d = 0; d < Dq; d++) s += qreg[d] * Ks[lane][d];

        // first-softmax probability
        const float sm = valid ? __expf(s - m1) * invl1 : 0.f;

        // warp inclusive scan -> running cumsum
        float ps = sm;
#pragma unroll
        for (int off = 1; off < 32; off <<= 1) {
            const float tv = __shfl_up_sync(0xffffffffu, ps, off);
            if (lane >= off) ps += tv;
        }
        const float Cj = Crun + ps;
        Crun += __shfl_sync(0xffffffffu, ps, 31);

        // distance decay (disttot == 1 exactly: masked entries are exact zeros)
        const float pd = valid ? fmaxf((1.f - Cj) * (float)(i - j), 0.f) : 0.f;
        float eff = __expf(gamma * sqrtf(pd));
        eff = fminf(fmaxf(eff, 1e-5f), 1e5f);
        const float s2 = valid ? s * eff : NEGINF;

        // online softmax-2 fused with V accumulation
        const float mn = fmaxf(m2, wmax(s2));
        const float alpha = __expf(m2 - mn);
        const float p = __expf(s2 - mn);      // masked -> 0
        l2 = l2 * alpha + wsum(p);
        o0 *= alpha; o1 *= alpha;
        m2 = mn;
#pragma unroll
        for (int jj = 0; jj < 32; jj++) {
            const float pj = __shfl_sync(0xffffffffu, p, jj);
            o0 += pj * Vs[jj][lane];
            o1 += pj * Vs[jj][lane + 32];
        }
    }

    const float invl2 = 1.f / l2;
    float* out = g_a + (size_t)(b * Sq + i) * Eq + h * Dq;
    out[lane]      = (i == 0) ? 0.f : o0 * invl2;
    out[lane + 32] = (i == 0) ? 0.f : o1 * invl2;
}

// ---------------------------------------------------------------------------
extern "C" void kernel_launch(void* const* d_in, const int* in_sizes, int n_in,
                              void* d_out, int out_size)
{
    const float* q      = (const float*)d_in[0];
    const float* k      = (const float*)d_in[1];
    const float* v      = (const float*)d_in[2];
    const float* Wk     = (const float*)d_in[3];
    const float* bk     = (const float*)d_in[4];
    const float* Wv     = (const float*)d_in[5];
    const float* bv     = (const float*)d_in[6];
    const float* Wo     = (const float*)d_in[7];
    const float* bo     = (const float*)d_in[8];
    const float* gammas = (const float*)d_in[9];

    dim3 gg(Eq / 128, BSq / 128);   // (4, 64)

    gemm_nt<<<gg, 256>>>(q, Wk, bk, nullptr, 0);                 // g_q
    gemm_nt<<<gg, 256>>>(k, Wk, bk, nullptr, 1);                 // g_k
    gemm_nt<<<gg, 256>>>(v, Wv, bv, nullptr, 2);                 // g_v
    attn_kernel<<<dim3(Sq / 8, Hq, Bq), 256>>>(gammas);          // g_a
    gemm_nt<<<gg, 256>>>(nullptr, Wo, bo, (float*)d_out, 3);     // final
}

// round 2
// speedup vs baseline: 1.1727x; 1.1727x over previous
#include <cuda_runtime.h>
#include <math.h>

// Problem constants
#define Bq 8
#define Sq 1024
#define Eq 512
#define Hq 8
#define Dq 64
#define BSq (Bq * Sq)
#define NW 8   // warps (query rows) per attention block

// Scratch (allocation-free: __device__ globals)
__device__ float g_q[BSq * Eq];   // q @ Wk^T + bk
__device__ float g_k[BSq * Eq];   // k @ Wk^T + bk
__device__ float g_v[BSq * Eq];   // v @ Wv^T + bv
__device__ float g_a[BSq * Eq];   // attention output (pre output-proj)

// ---------------------------------------------------------------------------
// GEMM: C[m,n] = sum_k A[m,k] * W[n,k] + bias[n]   (A:[8192,512], W:[512,512])
// 128x128 tile, BK=8, 256 threads, 8x8 microtile.
// out_sel: 0->g_q, 1->g_k, 2->g_v, 3->Cp.  Ap==nullptr -> read from g_a.
// ---------------------------------------------------------------------------
__global__ __launch_bounds__(256) void gemm_nt(const float* __restrict__ Ap,
                                               const float* __restrict__ W,
                                               const float* __restrict__ bias,
                                               float* __restrict__ Cp,
                                               int out_sel)
{
    const float* A = Ap ? Ap : g_a;
    float* C = (out_sel == 0) ? g_q : (out_sel == 1) ? g_k : (out_sel == 2) ? g_v : Cp;

    __shared__ float As[8][128];
    __shared__ float Ws[8][128];

    const int bm = blockIdx.y * 128;
    const int bn = blockIdx.x * 128;
    const int tid = threadIdx.x;
    const int lr = tid >> 1;          // 0..127: row in tile for loading
    const int lc = (tid & 1) * 4;     // 0 or 4: k-offset (float4)
    const int tm = (tid >> 4) * 8;    // microtile row base
    const int tn = (tid & 15) * 8;    // microtile col base

    float acc[8][8];
#pragma unroll
    for (int y = 0; y < 8; y++)
#pragma unroll
        for (int x = 0; x < 8; x++) acc[y][x] = 0.f;

    const float* Arow = A + (size_t)(bm + lr) * Eq + lc;
    const float* Wrow = W + (size_t)(bn + lr) * Eq + lc;

    for (int k0 = 0; k0 < Eq; k0 += 8) {
        float4 av = *(const float4*)(Arow + k0);
        float4 wv = *(const float4*)(Wrow + k0);
        __syncthreads();
        As[lc + 0][lr] = av.x; As[lc + 1][lr] = av.y;
        As[lc + 2][lr] = av.z; As[lc + 3][lr] = av.w;
        Ws[lc + 0][lr] = wv.x; Ws[lc + 1][lr] = wv.y;
        Ws[lc + 2][lr] = wv.z; Ws[lc + 3][lr] = wv.w;
        __syncthreads();
#pragma unroll
        for (int kk = 0; kk < 8; kk++) {
            float ar[8], br[8];
#pragma unroll
            for (int x = 0; x < 8; x++) { ar[x] = As[kk][tm + x]; br[x] = Ws[kk][tn + x]; }
#pragma unroll
            for (int y = 0; y < 8; y++)
#pragma unroll
                for (int x = 0; x < 8; x++) acc[y][x] += ar[y] * br[x];
        }
    }

#pragma unroll
    for (int y = 0; y < 8; y++) {
        float* crow = C + (size_t)(bm + tm + y) * Eq + bn + tn;
#pragma unroll
        for (int x = 0; x < 8; x++) crow[x] = acc[y][x] + bias[bn + tn + x];
    }
}

// ---------------------------------------------------------------------------
// Attention with distance-decay. One warp per query row, NW rows/block.
// Pass A: swizzled float4 K-dot, cache raw scores in shared, online (m1,l1).
// Pass B: read cached score, softmax1 prob, warp-scan cumsum, decay,
//         online softmax2 fused with vectorized PV (float2 per lane).
// ---------------------------------------------------------------------------
__device__ __forceinline__ float wmax(float v) {
#pragma unroll
    for (int o = 16; o > 0; o >>= 1) v = fmaxf(v, __shfl_xor_sync(0xffffffffu, v, o));
    return v;
}
__device__ __forceinline__ float wsum(float v) {
#pragma unroll
    for (int o = 16; o > 0; o >>= 1) v += __shfl_xor_sync(0xffffffffu, v, o);
    return v;
}

__global__ __launch_bounds__(32 * NW) void attn_kernel(const float* __restrict__ gammas)
{
    __shared__ float4 Ks4[32][16];       // XOR-16 swizzled K tile (8 KB)
    __shared__ float2 Vs2[32][32];       // V tile, float2 per (row, lanepair) (8 KB)
    __shared__ float  Ssc[NW][Sq];       // cached raw scores per warp (32 KB)

    const int b = blockIdx.z;
    const int h = blockIdx.y;
    const int r0 = (gridDim.x - 1 - blockIdx.x) * NW;   // heavy blocks first
    const int warp = threadIdx.x >> 5;
    const int lane = threadIdx.x & 31;
    const int i = r0 + warp;
    const int tid = threadIdx.x;
    const int NT = 32 * NW;

    // gamma = -softplus(gammas[h])
    const float gv = gammas[h];
    const float gamma = -(fmaxf(gv, 0.f) + log1pf(__expf(-fabsf(gv))));

    // q row in float4 registers, 1/sqrt(64) folded in
    float4 q4[16];
    const float4* qrow = (const float4*)(g_q + (size_t)(b * Sq + i) * Eq + h * Dq);
#pragma unroll
    for (int c = 0; c < 16; c++) {
        float4 t = qrow[c];
        t.x *= 0.125f; t.y *= 0.125f; t.z *= 0.125f; t.w *= 0.125f;
        q4[c] = t;
    }

    const int ntiles = (r0 + NW + 31) >> 5;
    const float NEGINF = -INFINITY;
    const int swz = lane & 15;

    // ---------------- Pass A: scores -> shared; online m1, l1 ----------------
    float m1 = NEGINF, l1 = 0.f;
    for (int t = 0; t < ntiles; t++) {
        const int jt = t << 5;
        __syncthreads();
        for (int idx = tid; idx < 512; idx += NT) {
            const int row = idx >> 4, c = idx & 15;
            Ks4[row][c ^ (row & 15)] =
                ((const float4*)(g_k + (size_t)(b * Sq + jt + row) * Eq + h * Dq))[c];
        }
        __syncthreads();

        float sa = 0.f, sb = 0.f, sc = 0.f, sd = 0.f;
#pragma unroll
        for (int c = 0; c < 16; c += 4) {
            float4 k0 = Ks4[lane][(c + 0) ^ swz];
            float4 k1 = Ks4[lane][(c + 1) ^ swz];
            float4 k2 = Ks4[lane][(c + 2) ^ swz];
            float4 k3 = Ks4[lane][(c + 3) ^ swz];
            sa += q4[c + 0].x * k0.x + q4[c + 0].y * k0.y + q4[c + 0].z * k0.z + q4[c + 0].w * k0.w;
            sb += q4[c + 1].x * k1.x + q4[c + 1].y * k1.y + q4[c + 1].z * k1.z + q4[c + 1].w * k1.w;
            sc += q4[c + 2].x * k2.x + q4[c + 2].y * k2.y + q4[c + 2].z * k2.z + q4[c + 2].w * k2.w;
            sd += q4[c + 3].x * k3.x + q4[c + 3].y * k3.y + q4[c + 3].z * k3.z + q4[c + 3].w * k3.w;
        }
        const float s = (sa + sb) + (sc + sd);

        const int j = jt + lane;
        Ssc[warp][j] = s;

        const float sv = (j <= i) ? s : NEGINF;
        const float mn = fmaxf(m1, wmax(sv));
        l1 = l1 * __expf(m1 - mn) + wsum(__expf(sv - mn));
        m1 = mn;
    }
    const float invl1 = 1.f / l1;

    // ---------------- Pass B: decay + softmax2 + PV ----------------
    float m2 = NEGINF, l2 = 0.f, Crun = 0.f;
    float ox = 0.f, oy = 0.f;
    for (int t = 0; t < ntiles; t++) {
        const int jt = t << 5;
        __syncthreads();
        for (int idx = tid; idx < 512; idx += NT) {
            const int row = idx >> 4, c = idx & 15;
            float4 vv = ((const float4*)(g_v + (size_t)(b * Sq + jt + row) * Eq + h * Dq))[c];
            Vs2[row][2 * c + 0] = make_float2(vv.x, vv.y);
            Vs2[row][2 * c + 1] = make_float2(vv.z, vv.w);
        }
        __syncthreads();

        const int j = jt + lane;
        const bool valid = (j <= i);
        const float s = Ssc[warp][j];

        // first-softmax probability (disttot == 1 exactly)
        const float sm = valid ? __expf(s - m1) * invl1 : 0.f;

        // warp inclusive scan -> running cumsum
        float ps = sm;
#pragma unroll
        for (int off = 1; off < 32; off <<= 1) {
            const float tv = __shfl_up_sync(0xffffffffu, ps, off);
            if (lane >= off) ps += tv;
        }
        const float Cj = Crun + ps;
        Crun += __shfl_sync(0xffffffffu, ps, 31);

        // distance decay
        const float pd = valid ? fmaxf((1.f - Cj) * (float)(i - j), 0.f) : 0.f;
        float eff = __expf(gamma * sqrtf(pd));
        eff = fminf(fmaxf(eff, 1e-5f), 1e5f);
        const float s2v = valid ? s * eff : NEGINF;

        // online softmax-2 fused with V accumulation
        const float mn = fmaxf(m2, wmax(s2v));
        const float alpha = __expf(m2 - mn);
        const float p = __expf(s2v - mn);     // masked -> 0
        l2 = l2 * alpha + wsum(p);
        ox *= alpha; oy *= alpha;
        m2 = mn;
#pragma unroll
        for (int jj = 0; jj < 32; jj++) {
            const float pj = __shfl_sync(0xffffffffu, p, jj);
            const float2 vv = Vs2[jj][lane];
            ox += pj * vv.x;
            oy += pj * vv.y;
        }
    }

    const float invl2 = 1.f / l2;
    float2* out2 = (float2*)(g_a + (size_t)(b * Sq + i) * Eq + h * Dq);
    float2 r;
    r.x = (i == 0) ? 0.f : ox * invl2;
    r.y = (i == 0) ? 0.f : oy * invl2;
    out2[lane] = r;
}

// ---------------------------------------------------------------------------
extern "C" void kernel_launch(void* const* d_in, const int* in_sizes, int n_in,
                              void* d_out, int out_size)
{
    const float* q      = (const float*)d_in[0];
    const float* k      = (const float*)d_in[1];
    const float* v      = (const float*)d_in[2];
    const float* Wk     = (const float*)d_in[3];
    const float* bk     = (const float*)d_in[4];
    const float* Wv     = (const float*)d_in[5];
    const float* bv     = (const float*)d_in[6];
    const float* Wo     = (const float*)d_in[7];
    const float* bo     = (const float*)d_in[8];
    const float* gammas = (const float*)d_in[9];

    dim3 gg(Eq / 128, BSq / 128);   // (4, 64)

    gemm_nt<<<gg, 256>>>(q, Wk, bk, nullptr, 0);                 // g_q
    gemm_nt<<<gg, 256>>>(k, Wk, bk, nullptr, 1);                 // g_k
    gemm_nt<<<gg, 256>>>(v, Wv, bv, nullptr, 2);                 // g_v
    attn_kernel<<<dim3(Sq / NW, Hq, Bq), 32 * NW>>>(gammas);     // g_a
    gemm_nt<<<gg, 256>>>(nullptr, Wo, bo, (float*)d_out, 3);     // final
}

// round 3
// speedup vs baseline: 1.8520x; 1.5792x over previous
#include <cuda_runtime.h>
#include <math.h>

// Problem constants
#define Bq 8
#define Sq 1024
#define Eq 512
#define Hq 8
#define Dq 64
#define BSq (Bq * Sq)

// Scratch (allocation-free: __device__ globals)
__device__ float g_q[BSq * Eq];           // q @ Wk^T + bk
__device__ float g_k[BSq * Eq];           // k @ Wk^T + bk
__device__ float g_v[BSq * Eq];           // v @ Wv^T + bv
__device__ float g_a[BSq * Eq];           // attention output (pre output-proj)
__device__ float g_s[(size_t)64 * Sq * Sq]; // scores -> probs, per (b,h) [1024x1024]

// ---------------------------------------------------------------------------
// Projection GEMM: C[m,n] = sum_k A[m,k]*W[n,k] + bias[n]  (A:[8192,512])
// ---------------------------------------------------------------------------
__global__ __launch_bounds__(256) void gemm_nt(const float* __restrict__ Ap,
                                               const float* __restrict__ W,
                                               const float* __restrict__ bias,
                                               float* __restrict__ Cp,
                                               int out_sel)
{
    const float* A = Ap ? Ap : g_a;
    float* C = (out_sel == 0) ? g_q : (out_sel == 1) ? g_k : (out_sel == 2) ? g_v : Cp;

    __shared__ float As[8][128];
    __shared__ float Ws[8][128];

    const int bm = blockIdx.y * 128;
    const int bn = blockIdx.x * 128;
    const int tid = threadIdx.x;
    const int lr = tid >> 1;
    const int lc = (tid & 1) * 4;
    const int tm = (tid >> 4) * 8;
    const int tn = (tid & 15) * 8;

    float acc[8][8];
#pragma unroll
    for (int y = 0; y < 8; y++)
#pragma unroll
        for (int x = 0; x < 8; x++) acc[y][x] = 0.f;

    const float* Arow = A + (size_t)(bm + lr) * Eq + lc;
    const float* Wrow = W + (size_t)(bn + lr) * Eq + lc;

    for (int k0 = 0; k0 < Eq; k0 += 8) {
        float4 av = *(const float4*)(Arow + k0);
        float4 wv = *(const float4*)(Wrow + k0);
        __syncthreads();
        As[lc + 0][lr] = av.x; As[lc + 1][lr] = av.y;
        As[lc + 2][lr] = av.z; As[lc + 3][lr] = av.w;
        Ws[lc + 0][lr] = wv.x; Ws[lc + 1][lr] = wv.y;
        Ws[lc + 2][lr] = wv.z; Ws[lc + 3][lr] = wv.w;
        __syncthreads();
#pragma unroll
        for (int kk = 0; kk < 8; kk++) {
            float ar[8], br[8];
#pragma unroll
            for (int x = 0; x < 8; x++) { ar[x] = As[kk][tm + x]; br[x] = Ws[kk][tn + x]; }
#pragma unroll
            for (int y = 0; y < 8; y++)
#pragma unroll
                for (int x = 0; x < 8; x++) acc[y][x] += ar[y] * br[x];
        }
    }

#pragma unroll
    for (int y = 0; y < 8; y++) {
        float* crow = C + (size_t)(bm + tm + y) * Eq + bn + tn;
#pragma unroll
        for (int x = 0; x < 8; x++) crow[x] = acc[y][x] + bias[bn + tn + x];
    }
}

// ---------------------------------------------------------------------------
// QK^T: S[bh][i][j] = (1/8) * sum_d q[i][d]*k[j][d].  Causal: skip tiles by<bx.
// A/B rows have stride Eq (head slice), K extent = 64.
// ---------------------------------------------------------------------------
__global__ __launch_bounds__(256) void qk_gemm()
{
    const int bx = blockIdx.x;   // j tile
    const int by = blockIdx.y;   // i tile
    if (by < bx) return;
    const int bh = blockIdx.z;
    const int b = bh >> 3, h = bh & 7;

    const float* A = g_q + (size_t)b * Sq * Eq + h * Dq;
    const float* B = g_k + (size_t)b * Sq * Eq + h * Dq;
    float* C = g_s + ((size_t)bh << 20);

    __shared__ float As[8][128];
    __shared__ float Ws[8][128];

    const int bm = by * 128;
    const int bn = bx * 128;
    const int tid = threadIdx.x;
    const int lr = tid >> 1;
    const int lc = (tid & 1) * 4;
    const int tm = (tid >> 4) * 8;
    const int tn = (tid & 15) * 8;

    float acc[8][8];
#pragma unroll
    for (int y = 0; y < 8; y++)
#pragma unroll
        for (int x = 0; x < 8; x++) acc[y][x] = 0.f;

    const float* Arow = A + (size_t)(bm + lr) * Eq + lc;
    const float* Brow = B + (size_t)(bn + lr) * Eq + lc;

#pragma unroll
    for (int k0 = 0; k0 < Dq; k0 += 8) {
        float4 av = *(const float4*)(Arow + k0);
        float4 wv = *(const float4*)(Brow + k0);
        __syncthreads();
        As[lc + 0][lr] = av.x; As[lc + 1][lr] = av.y;
        As[lc + 2][lr] = av.z; As[lc + 3][lr] = av.w;
        Ws[lc + 0][lr] = wv.x; Ws[lc + 1][lr] = wv.y;
        Ws[lc + 2][lr] = wv.z; Ws[lc + 3][lr] = wv.w;
        __syncthreads();
#pragma unroll
        for (int kk = 0; kk < 8; kk++) {
            float ar[8], br[8];
#pragma unroll
            for (int x = 0; x < 8; x++) { ar[x] = As[kk][tm + x]; br[x] = Ws[kk][tn + x]; }
#pragma unroll
            for (int y = 0; y < 8; y++)
#pragma unroll
                for (int x = 0; x < 8; x++) acc[y][x] += ar[y] * br[x];
        }
    }

#pragma unroll
    for (int y = 0; y < 8; y++) {
        float* crow = C + (size_t)(bm + tm + y) * Sq + bn + tn;
#pragma unroll
        for (int x = 0; x < 8; x += 4) {
            float4 o;
            o.x = acc[y][x + 0] * 0.125f;
            o.y = acc[y][x + 1] * 0.125f;
            o.z = acc[y][x + 2] * 0.125f;
            o.w = acc[y][x + 3] * 0.125f;
            *(float4*)(crow + x) = o;
        }
    }
}

// ---------------------------------------------------------------------------
// Softmax + distance-decay + second softmax; row in registers (32 floats/lane).
// In-place: reads scores from g_s row, writes final probs back to same row.
// ---------------------------------------------------------------------------
__device__ __forceinline__ float wmax(float v) {
#pragma unroll
    for (int o = 16; o > 0; o >>= 1) v = fmaxf(v, __shfl_xor_sync(0xffffffffu, v, o));
    return v;
}
__device__ __forceinline__ float wsum(float v) {
#pragma unroll
    for (int o = 16; o > 0; o >>= 1) v += __shfl_xor_sync(0xffffffffu, v, o);
    return v;
}

__global__ __launch_bounds__(256) void softmax_decay(const float* __restrict__ gammas)
{
    const int warp = threadIdx.x >> 5;
    const int lane = threadIdx.x & 31;
    const int r = blockIdx.x * 8 + warp;       // global row over [bh][i]
    const int i = r & (Sq - 1);
    const int h = (r >> 10) & (Hq - 1);
    float* Srow = g_s + (size_t)r * Sq;

    const float gv = gammas[h];
    const float gamma = -(fmaxf(gv, 0.f) + log1pf(__expf(-fabsf(gv))));
    const float NEGINF = -INFINITY;

    const int j0 = lane * 32;
    float s[32];
#pragma unroll
    for (int t = 0; t < 8; t++) ((float4*)s)[t] = ((const float4*)(Srow + j0))[t];
#pragma unroll
    for (int t = 0; t < 32; t++) if (j0 + t > i) s[t] = NEGINF;

    // softmax-1 stats
    float m1 = NEGINF;
#pragma unroll
    for (int t = 0; t < 32; t++) m1 = fmaxf(m1, s[t]);
    m1 = wmax(m1);

    float p[32];
    float ls = 0.f;
#pragma unroll
    for (int t = 0; t < 32; t++) { p[t] = __expf(s[t] - m1); ls += p[t]; }
    const float inv1 = 1.f / wsum(ls);

    // inclusive scan of unnormalized probs: local prefix, then warp prefix of totals
#pragma unroll
    for (int t = 1; t < 32; t++) p[t] += p[t - 1];
    float tot = p[31];
    float x = tot;
#pragma unroll
    for (int off = 1; off < 32; off <<= 1) {
        const float tv = __shfl_up_sync(0xffffffffu, x, off);
        if (lane >= off) x += tv;
    }
    const float excl = x - tot;

    // decay + scaled scores (in place into s)
    float m2 = NEGINF;
#pragma unroll
    for (int t = 0; t < 32; t++) {
        const int j = j0 + t;
        const float Cj = (excl + p[t]) * inv1;
        const float pd = fmaxf((1.f - Cj) * (float)(i - j), 0.f);
        float eff = __expf(gamma * sqrtf(pd));
        eff = fminf(fmaxf(eff, 1e-5f), 1e5f);
        s[t] *= eff;                  // -inf stays -inf
        m2 = fmaxf(m2, s[t]);
    }
    m2 = wmax(m2);

    float l2 = 0.f;
#pragma unroll
    for (int t = 0; t < 32; t++) { p[t] = __expf(s[t] - m2); l2 += p[t]; }
    const float scale = ((i == 0) ? 0.f : 1.f) / wsum(l2);
#pragma unroll
    for (int t = 0; t < 32; t++) p[t] *= scale;
#pragma unroll
    for (int t = 0; t < 8; t++) ((float4*)(Srow + j0))[t] = ((float4*)p)[t];
}

// ---------------------------------------------------------------------------
// PV: out[i][d] = sum_j P[i][j] * V[j][d].  Tile 128(i) x 64(d), BK=16,
// causal K extent = bm+128. 256 threads, 8x4 microtile.
// ---------------------------------------------------------------------------
__global__ __launch_bounds__(256) void pv_gemm()
{
    __shared__ float Ps[16][132];   // [k][i], padded
    __shared__ float Vs[16][64];    // [k][d]

    const int bh = blockIdx.y;
    const int itile = gridDim.x - 1 - blockIdx.x;   // heavy tiles first
    const int bm = itile * 128;
    const int b = bh >> 3, h = bh & 7;

    const float* P = g_s + ((size_t)bh << 20);
    const float* V = g_v + (size_t)b * Sq * Eq + h * Dq;
    float* C = g_a + (size_t)b * Sq * Eq + h * Dq;

    const int tid = threadIdx.x;
    const int prow = tid & 127;          // i-local for P load
    const int pcg  = (tid >> 7) * 8;     // k col-group: 0 or 8
    const int vrow = tid >> 4;           // 0..15 for V load
    const int vcol = (tid & 15) * 4;
    const int tm = (tid >> 4) * 8;
    const int tn = (tid & 15) * 4;

    float acc[8][4];
#pragma unroll
    for (int y = 0; y < 8; y++)
#pragma unroll
        for (int xx = 0; xx < 4; xx++) acc[y][xx] = 0.f;

    const int kmax = bm + 128;
    const float* Prow = P + (size_t)(bm + prow) * Sq + pcg;

    for (int k0 = 0; k0 < kmax; k0 += 16) {
        float4 pa = *(const float4*)(Prow + k0);
        float4 pb = *(const float4*)(Prow + k0 + 4);
        float4 vv = *(const float4*)(V + (size_t)(k0 + vrow) * Eq + vcol);
        __syncthreads();
        Ps[pcg + 0][prow] = pa.x; Ps[pcg + 1][prow] = pa.y;
        Ps[pcg + 2][prow] = pa.z; Ps[pcg + 3][prow] = pa.w;
        Ps[pcg + 4][prow] = pb.x; Ps[pcg + 5][prow] = pb.y;
        Ps[pcg + 6][prow] = pb.z; Ps[pcg + 7][prow] = pb.w;
        *(float4*)&Vs[vrow][vcol] = vv;
        __syncthreads();
#pragma unroll
        for (int kk = 0; kk < 16; kk++) {
            float ar[8], br[4];
            *(float4*)(ar + 0) = *(const float4*)&Ps[kk][tm];
            *(float4*)(ar + 4) = *(const float4*)&Ps[kk][tm + 4];
            *(float4*)(br)     = *(const float4*)&Vs[kk][tn];
#pragma unroll
            for (int y = 0; y < 8; y++)
#pragma unroll
                for (int xx = 0; xx < 4; xx++) acc[y][xx] += ar[y] * br[xx];
        }
    }

#pragma unroll
    for (int y = 0; y < 8; y++) {
        float4 o;
        o.x = acc[y][0]; o.y = acc[y][1]; o.z = acc[y][2]; o.w = acc[y][3];
        *(float4*)(C + (size_t)(bm + tm + y) * Eq + tn) = o;
    }
}

// ---------------------------------------------------------------------------
extern "C" void kernel_launch(void* const* d_in, const int* in_sizes, int n_in,
                              void* d_out, int out_size)
{
    const float* q      = (const float*)d_in[0];
    const float* k      = (const float*)d_in[1];
    const float* v      = (const float*)d_in[2];
    const float* Wk     = (const float*)d_in[3];
    const float* bk     = (const float*)d_in[4];
    const float* Wv     = (const float*)d_in[5];
    const float* bv     = (const float*)d_in[6];
    const float* Wo     = (const float*)d_in[7];
    const float* bo     = (const float*)d_in[8];
    const float* gammas = (const float*)d_in[9];

    dim3 gg(Eq / 128, BSq / 128);   // (4, 64)

    gemm_nt<<<gg, 256>>>(q, Wk, bk, nullptr, 0);                 // g_q
    gemm_nt<<<gg, 256>>>(k, Wk, bk, nullptr, 1);                 // g_k
    gemm_nt<<<gg, 256>>>(v, Wv, bv, nullptr, 2);                 // g_v
    qk_gemm<<<dim3(8, 8, 64), 256>>>();                          // g_s = scores
    softmax_decay<<<(64 * Sq) / 8, 256>>>(gammas);               // g_s = probs
    pv_gemm<<<dim3(8, 64), 256>>>();                             // g_a
    gemm_nt<<<gg, 256>>>(nullptr, Wo, bo, (float*)d_out, 3);     // final
}

// round 5
// speedup vs baseline: 3.1854x; 1.7200x over previous
#include <cuda_runtime.h>
#include <cuda_bf16.h>
#include <math.h>
#include <stdint.h>

// Problem constants
#define Bq 8
#define Sq 1024
#define Eq 512
#define Hq 8
#define Dq 64
#define BSq (Bq * Sq)

// Scratch (allocation-free: __device__ globals)
__device__ float g_q[BSq * Eq];             // q @ Wk^T + bk
__device__ float g_k[BSq * Eq];             // k @ Wk^T + bk
__device__ float g_vT[64 * Dq * Sq];        // v @ Wv^T + bv, TRANSPOSED: [bh][d][s]
__device__ float g_a[BSq * Eq];             // attention output (pre output-proj)
__device__ float g_s[(size_t)64 * Sq * Sq]; // scores -> probs, per (b,h) [1024x1024]

#define RS 80   // smem row stride in bytes: 32 bf16 (64B) + 16B pad (conflict-free ldmatrix)

__device__ __forceinline__ uint32_t smem_u32(const void* p) {
    uint32_t a;
    asm("{ .reg .u64 t; cvta.to.shared.u64 t, %1; cvt.u32.u64 %0, t; }" : "=r"(a) : "l"(p));
    return a;
}

#define LDSM4(r, a) asm volatile( \
    "ldmatrix.sync.aligned.m8n8.x4.shared.b16 {%0,%1,%2,%3}, [%4];" \
    : "=r"((r)[0]), "=r"((r)[1]), "=r"((r)[2]), "=r"((r)[3]) : "r"(a))

#define MMA(d, a, b0, b1) asm volatile( \
    "mma.sync.aligned.m16n8k16.row.col.f32.bf16.bf16.f32 " \
    "{%0,%1,%2,%3}, {%4,%5,%6,%7}, {%8,%9}, {%0,%1,%2,%3};" \
    : "+f"((d)[0]), "+f"((d)[1]), "+f"((d)[2]), "+f"((d)[3]) \
    : "r"((a)[0]), "r"((a)[1]), "r"((a)[2]), "r"((a)[3]), "r"(b0), "r"(b1))

// Load R x 32 fp32 tile -> bf16 hi/lo planes in smem (row stride RS).
template<int R>
__device__ __forceinline__ void load_split(const float* __restrict__ src, int ld,
                                           char* hi, char* lo, int tid) {
#pragma unroll
    for (int it = 0; it < (R * 8) / 256; ++it) {
        const int idx = tid + it * 256;
        const int row = idx >> 3, c4 = (idx & 7) << 2;
        float4 v = *(const float4*)(src + (size_t)row * ld + c4);
        __nv_bfloat162 h01 = __floats2bfloat162_rn(v.x, v.y);
        __nv_bfloat162 h23 = __floats2bfloat162_rn(v.z, v.w);
        float2 f01 = __bfloat1622float2(h01);
        float2 f23 = __bfloat1622float2(h23);
        __nv_bfloat162 l01 = __floats2bfloat162_rn(v.x - f01.x, v.y - f01.y);
        __nv_bfloat162 l23 = __floats2bfloat162_rn(v.z - f23.x, v.w - f23.y);
        const uint32_t off = (uint32_t)(row * RS + (c4 << 1));
        *(uint2*)(hi + off) = make_uint2(*(uint32_t*)&h01, *(uint32_t*)&h23);
        *(uint2*)(lo + off) = make_uint2(*(uint32_t*)&l01, *(uint32_t*)&l23);
    }
}

// Core: acc += A[128,K] . B[BROWS,K]^T with 2-term bf16 split (3 MMA products).
// Warp grid 2(m) x 4(n); warp tile 64 x (NT*8).
template<int BROWS, int NT>
__device__ __forceinline__ void mma_core(char* sm, uint32_t smb,
                                         const float* A, int lda,
                                         const float* B, int ldb,
                                         int nchunks, int tid,
                                         float acc[4][NT][4]) {
    const int AH = 0, AL = 128 * RS, BH = 2 * 128 * RS, BL = 2 * 128 * RS + BROWS * RS;
    const int wid = tid >> 5, lane = tid & 31;
    const int wm = wid & 1, wn = wid >> 1;
    const int WN = NT * 8;
    const uint32_t aoff = (uint32_t)((wm * 64 + (lane & 15)) * RS + ((lane >> 4) << 4));
    const uint32_t bi = lane >> 3;
    const uint32_t boff = (uint32_t)((wn * WN + ((bi >> 1) << 3) + (lane & 7)) * RS + ((bi & 1) << 4));

    for (int c = 0; c < nchunks; ++c) {
        __syncthreads();
        load_split<128>(A + c * 32, lda, sm + AH, sm + AL, tid);
        load_split<BROWS>(B + c * 32, ldb, sm + BH, sm + BL, tid);
        __syncthreads();
#pragma unroll
        for (int s = 0; s < 2; ++s) {
            uint32_t ah[4][4], al[4][4];
            uint32_t bh[(NT + 1) / 2][4], bl[(NT + 1) / 2][4];
            const uint32_t so = s * 32;
#pragma unroll
            for (int mt = 0; mt < 4; ++mt) {
                LDSM4(ah[mt], smb + AH + aoff + mt * 16 * RS + so);
                LDSM4(al[mt], smb + AL + aoff + mt * 16 * RS + so);
            }
#pragma unroll
            for (int p = 0; p < (NT + 1) / 2; ++p) {
                LDSM4(bh[p], smb + BH + boff + p * 16 * RS + so);
                LDSM4(bl[p], smb + BL + boff + p * 16 * RS + so);
            }
#pragma unroll
            for (int mt = 0; mt < 4; ++mt)
#pragma unroll
                for (int nt = 0; nt < NT; ++nt) {
                    const uint32_t b0h = bh[nt >> 1][(nt & 1) * 2];
                    const uint32_t b1h = bh[nt >> 1][(nt & 1) * 2 + 1];
                    const uint32_t b0l = bl[nt >> 1][(nt & 1) * 2];
                    const uint32_t b1l = bl[nt >> 1][(nt & 1) * 2 + 1];
                    MMA(acc[mt][nt], ah[mt], b0h, b1h);   // hi*hi
                    MMA(acc[mt][nt], al[mt], b0h, b1h);   // lo*hi
                    MMA(acc[mt][nt], ah[mt], b0l, b1l);   // hi*lo
                }
        }
    }
}

// ---------------------------------------------------------------------------
// Projection: C[m,n] = A[m,:].W[n,:] + bias[n].
// csel: 0->g_q, 1->g_k, 2->g_vT (transposed), 3->Cp.  Ain==nullptr -> g_a.
// ---------------------------------------------------------------------------
__global__ __launch_bounds__(256) void proj_mma(const float* __restrict__ Ain,
                                                const float* __restrict__ W,
                                                const float* __restrict__ bias,
                                                float* __restrict__ Cp, int csel) {
    __shared__ __align__(16) char sm[40960];
    const uint32_t smb = smem_u32(sm);
    const int tid = threadIdx.x, wid = tid >> 5, lane = tid & 31;
    const int wm = wid & 1, wn = wid >> 1;
    const int bm = blockIdx.y * 128, bn = blockIdx.x * 128;

    const float* A = (Ain ? Ain : g_a) + (size_t)bm * Eq;
    const float* B = W + (size_t)bn * Eq;

    float acc[4][4][4];
#pragma unroll
    for (int a = 0; a < 4; ++a)
#pragma unroll
        for (int b = 0; b < 4; ++b)
#pragma unroll
            for (int c = 0; c < 4; ++c) acc[a][b][c] = 0.f;

    mma_core<128, 4>(sm, smb, A, Eq, B, Eq, 16, tid, acc);
    __syncthreads();

    if (csel != 2) {
        float* C = (csel == 0) ? g_q : (csel == 1) ? g_k : Cp;
#pragma unroll
        for (int mt = 0; mt < 4; ++mt)
#pragma unroll
            for (int nt = 0; nt < 4; ++nt) {
                const int row = bm + wm * 64 + mt * 16 + (lane >> 2);
                const int col = bn + wn * 32 + nt * 8 + ((lane & 3) << 1);
                const float2 bb = *(const float2*)(bias + col);
                float2 o0, o1;
                o0.x = acc[mt][nt][0] + bb.x; o0.y = acc[mt][nt][1] + bb.y;
                o1.x = acc[mt][nt][2] + bb.x; o1.y = acc[mt][nt][3] + bb.y;
                *(float2*)(C + (size_t)row * Eq + col) = o0;
                *(float2*)(C + (size_t)(row + 8) * Eq + col) = o1;
            }
    } else {
        // transpose through smem into g_vT[bh][d][s]
        float (*smt)[65] = (float(*)[65])sm;
#pragma unroll
        for (int hf = 0; hf < 2; ++hf) {
            if ((wn >> 1) == hf) {
#pragma unroll
                for (int mt = 0; mt < 4; ++mt)
#pragma unroll
                    for (int nt = 0; nt < 4; ++nt) {
                        const int row = wm * 64 + mt * 16 + (lane >> 2);
                        const int colL = (wn & 1) * 32 + nt * 8 + ((lane & 3) << 1);
                        const int colG = bn + hf * 64 + colL;
                        const float2 bb = *(const float2*)(bias + colG);
                        smt[row][colL] = acc[mt][nt][0] + bb.x;
                        smt[row][colL + 1] = acc[mt][nt][1] + bb.y;
                        smt[row + 8][colL] = acc[mt][nt][2] + bb.x;
                        smt[row + 8][colL + 1] = acc[mt][nt][3] + bb.y;
                    }
            }
            __syncthreads();
            {
                const int colL = tid & 63, seg = (tid >> 6) << 5;
                const int n = bn + hf * 64 + colL;
                float* dst = g_vT + ((size_t)((bm >> 10) * 8 + (n >> 6)) << 16) +
                             ((size_t)(n & 63) << 10) + (bm & 1023) + seg;
#pragma unroll
                for (int i = 0; i < 8; ++i) {
                    float4 o = make_float4(smt[seg + 4 * i][colL], smt[seg + 4 * i + 1][colL],
                                           smt[seg + 4 * i + 2][colL], smt[seg + 4 * i + 3][colL]);
                    *(float4*)(dst + 4 * i) = o;
                }
            }
            __syncthreads();
        }
    }
}

// ---------------------------------------------------------------------------
// QK^T: S = (1/8) q . k^T per (b,h); causal tile skip. K extent 64 (2 chunks).
// ---------------------------------------------------------------------------
__global__ __launch_bounds__(256) void qk_mma() {
    const int bx = blockIdx.x, by = blockIdx.y;
    if (by < bx) return;
    __shared__ __align__(16) char sm[40960];
    const uint32_t smb = smem_u32(sm);
    const int tid = threadIdx.x, wid = tid >> 5, lane = tid & 31;
    const int wm = wid & 1, wn = wid >> 1;
    const int bh = blockIdx.z, b = bh >> 3, h = bh & 7;
    const int bm = by * 128, bn = bx * 128;

    const float* A = g_q + (size_t)b * Sq * Eq + (size_t)bm * Eq + h * Dq;
    const float* B = g_k + (size_t)b * Sq * Eq + (size_t)bn * Eq + h * Dq;

    float acc[4][4][4];
#pragma unroll
    for (int a = 0; a < 4; ++a)
#pragma unroll
        for (int c = 0; c < 4; ++c)
#pragma unroll
            for (int d = 0; d < 4; ++d) acc[a][c][d] = 0.f;

    mma_core<128, 4>(sm, smb, A, Eq, B, Eq, 2, tid, acc);

    float* S = g_s + ((size_t)bh << 20);
#pragma unroll
    for (int mt = 0; mt < 4; ++mt)
#pragma unroll
        for (int nt = 0; nt < 4; ++nt) {
            const int row = bm + wm * 64 + mt * 16 + (lane >> 2);
            const int col = bn + wn * 32 + nt * 8 + ((lane & 3) << 1);
            float2 o0, o1;
            o0.x = acc[mt][nt][0] * 0.125f; o0.y = acc[mt][nt][1] * 0.125f;
            o1.x = acc[mt][nt][2] * 0.125f; o1.y = acc[mt][nt][3] * 0.125f;
            *(float2*)(S + (size_t)row * Sq + col) = o0;
            *(float2*)(S + (size_t)(row + 8) * Sq + col) = o1;
        }
}

// ---------------------------------------------------------------------------
// PV: out[i,d] = sum_j P[i,j] * VT[d,j].  BN=64, K extent = bm+128 (causal).
// ---------------------------------------------------------------------------
__global__ __launch_bounds__(256) void pv_mma() {
    __shared__ __align__(16) char sm[30720];
    const uint32_t smb = smem_u32(sm);
    const int tid = threadIdx.x, wid = tid >> 5, lane = tid & 31;
    const int wm = wid & 1, wn = wid >> 1;
    const int bh = blockIdx.y, b = bh >> 3, h = bh & 7;
    const int bm = (7 - (int)blockIdx.x) * 128;   // heavy tiles first

    const float* A = g_s + ((size_t)bh << 20) + (size_t)bm * Sq;
    const float* B = g_vT + (size_t)bh * (Dq * Sq);

    float acc[4][2][4];
#pragma unroll
    for (int a = 0; a < 4; ++a)
#pragma unroll
        for (int c = 0; c < 2; ++c)
#pragma unroll
            for (int d = 0; d < 4; ++d) acc[a][c][d] = 0.f;

    mma_core<64, 2>(sm, smb, A, Sq, B, Sq, bm / 32 + 4, tid, acc);

#pragma unroll
    for (int mt = 0; mt < 4; ++mt)
#pragma unroll
        for (int nt = 0; nt < 2; ++nt) {
            const int row = b * Sq + bm + wm * 64 + mt * 16 + (lane >> 2);
            const int col = h * Dq + wn * 16 + nt * 8 + ((lane & 3) << 1);
            float2 o0, o1;
            o0.x = acc[mt][nt][0]; o0.y = acc[mt][nt][1];
            o1.x = acc[mt][nt][2]; o1.y = acc[mt][nt][3];
            *(float2*)(g_a + (size_t)row * Eq + col) = o0;
            *(float2*)(g_a + (size_t)(row + 8) * Eq + col) = o1;
        }
}

// ---------------------------------------------------------------------------
// Softmax + distance-decay + second softmax (row in registers).
// ---------------------------------------------------------------------------
__device__ __forceinline__ float wmax(float v) {
#pragma unroll
    for (int o = 16; o > 0; o >>= 1) v = fmaxf(v, __shfl_xor_sync(0xffffffffu, v, o));
    return v;
}
__device__ __forceinline__ float wsum(float v) {
#pragma unroll
    for (int o = 16; o > 0; o >>= 1) v += __shfl_xor_sync(0xffffffffu, v, o);
    return v;
}

__global__ __launch_bounds__(256) void softmax_decay(const float* __restrict__ gammas) {
    const int warp = threadIdx.x >> 5;
    const int lane = threadIdx.x & 31;
    const int r = blockIdx.x * 8 + warp;
    const int i = r & (Sq - 1);
    const int h = (r >> 10) & (Hq - 1);
    float* Srow = g_s + (size_t)r * Sq;

    const float gv = gammas[h];
    const float gamma = -(fmaxf(gv, 0.f) + log1pf(__expf(-fabsf(gv))));
    const float NEGINF = -INFINITY;

    const int j0 = lane * 32;
    float s[32];
#pragma unroll
    for (int t = 0; t < 8; t++) ((float4*)s)[t] = ((const float4*)(Srow + j0))[t];
#pragma unroll
    for (int t = 0; t < 32; t++) if (j0 + t > i) s[t] = NEGINF;

    float m1 = NEGINF;
#pragma unroll
    for (int t = 0; t < 32; t++) m1 = fmaxf(m1, s[t]);
    m1 = wmax(m1);

    float p[32];
    float ls = 0.f;
#pragma unroll
    for (int t = 0; t < 32; t++) { p[t] = __expf(s[t] - m1); ls += p[t]; }
    const float inv1 = 1.f / wsum(ls);

#pragma unroll
    for (int t = 1; t < 32; t++) p[t] += p[t - 1];
    float tot = p[31];
    float x = tot;
#pragma unroll
    for (int off = 1; off < 32; off <<= 1) {
        const float tv = __shfl_up_sync(0xffffffffu, x, off);
        if (lane >= off) x += tv;
    }
    const float excl = x - tot;

    float m2 = NEGINF;
#pragma unroll
    for (int t = 0; t < 32; t++) {
        const int j = j0 + t;
        const float Cj = (excl + p[t]) * inv1;
        const float pd = fmaxf((1.f - Cj) * (float)(i - j), 0.f);
        float eff = __expf(gamma * sqrtf(pd));
        eff = fminf(fmaxf(eff, 1e-5f), 1e5f);
        s[t] *= eff;
        m2 = fmaxf(m2, s[t]);
    }
    m2 = wmax(m2);

    float l2 = 0.f;
#pragma unroll
    for (int t = 0; t < 32; t++) { p[t] = __expf(s[t] - m2); l2 += p[t]; }
    const float scale = ((i == 0) ? 0.f : 1.f) / wsum(l2);
#pragma unroll
    for (int t = 0; t < 32; t++) p[t] *= scale;
#pragma unroll
    for (int t = 0; t < 8; t++) ((float4*)(Srow + j0))[t] = ((float4*)p)[t];
}

// ---------------------------------------------------------------------------
extern "C" void kernel_launch(void* const* d_in, const int* in_sizes, int n_in,
                              void* d_out, int out_size) {
    const float* q      = (const float*)d_in[0];
    const float* k      = (const float*)d_in[1];
    const float* v      = (const float*)d_in[2];
    const float* Wk     = (const float*)d_in[3];
    const float* bk     = (const float*)d_in[4];
    const float* Wv     = (const float*)d_in[5];
    const float* bv     = (const float*)d_in[6];
    const float* Wo     = (const float*)d_in[7];
    const float* bo     = (const float*)d_in[8];
    const float* gammas = (const float*)d_in[9];

    dim3 gg(4, 64);
    proj_mma<<<gg, 256>>>(q, Wk, bk, nullptr, 0);                // g_q
    proj_mma<<<gg, 256>>>(k, Wk, bk, nullptr, 1);                // g_k
    proj_mma<<<gg, 256>>>(v, Wv, bv, nullptr, 2);                // g_vT
    qk_mma<<<dim3(8, 8, 64), 256>>>();                           // g_s = scores
    softmax_decay<<<(64 * Sq) / 8, 256>>>(gammas);               // g_s = probs
    pv_mma<<<dim3(8, 64), 256>>>();                              // g_a
    proj_mma<<<gg, 256>>>(nullptr, Wo, bo, (float*)d_out, 3);    // final
}

// round 6
// speedup vs baseline: 3.5414x; 1.1117x over previous
#include <cuda_runtime.h>
#include <cuda_bf16.h>
#include <math.h>
#include <stdint.h>

// Problem constants
#define Bq 8
#define Sq 1024
#define Eq 512
#define Hq 8
#define Dq 64
#define BSq (Bq * Sq)

// Scratch (allocation-free: __device__ globals)
__device__ float g_q[BSq * Eq];             // q @ Wk^T + bk
__device__ float g_k[BSq * Eq];             // k @ Wk^T + bk
__device__ float g_vT[64 * Dq * Sq];        // v @ Wv^T + bv, TRANSPOSED: [bh][d][s]
__device__ float g_a[BSq * Eq];             // attention output (pre output-proj)
__device__ float g_s[(size_t)64 * Sq * Sq]; // scores -> probs, per (b,h) [1024x1024]

#define RS 80   // smem row stride in bytes: 32 bf16 (64B) + 16B pad (conflict-free ldmatrix)

__device__ __forceinline__ uint32_t smem_u32(const void* p) {
    uint32_t a;
    asm("{ .reg .u64 t; cvta.to.shared.u64 t, %1; cvt.u32.u64 %0, t; }" : "=r"(a) : "l"(p));
    return a;
}

#define LDSM4(r, a) asm volatile( \
    "ldmatrix.sync.aligned.m8n8.x4.shared.b16 {%0,%1,%2,%3}, [%4];" \
    : "=r"((r)[0]), "=r"((r)[1]), "=r"((r)[2]), "=r"((r)[3]) : "r"(a))

#define MMA(d, a, b0, b1) asm volatile( \
    "mma.sync.aligned.m16n8k16.row.col.f32.bf16.bf16.f32 " \
    "{%0,%1,%2,%3}, {%4,%5,%6,%7}, {%8,%9}, {%0,%1,%2,%3};" \
    : "+f"((d)[0]), "+f"((d)[1]), "+f"((d)[2]), "+f"((d)[3]) \
    : "r"((a)[0]), "r"((a)[1]), "r"((a)[2]), "r"((a)[3]), "r"(b0), "r"(b1))

// Gather R x 32 fp32 tile into registers (R*8/256 float4 per thread).
template<int R>
__device__ __forceinline__ void ldg_tile(const float* __restrict__ src, int ld,
                                         int tid, float4* v) {
#pragma unroll
    for (int it = 0; it < (R * 8) / 256; ++it) {
        const int idx = tid + it * 256;
        const int row = idx >> 3, c4 = (idx & 7) << 2;
        v[it] = *(const float4*)(src + (size_t)row * ld + c4);
    }
}

// Convert registers -> bf16 hi/lo planes in smem (row stride RS).
template<int R>
__device__ __forceinline__ void sts_split(const float4* v, char* hi, char* lo, int tid) {
#pragma unroll
    for (int it = 0; it < (R * 8) / 256; ++it) {
        const int idx = tid + it * 256;
        const int row = idx >> 3, c4 = (idx & 7) << 2;
        const float4 x = v[it];
        __nv_bfloat162 h01 = __floats2bfloat162_rn(x.x, x.y);
        __nv_bfloat162 h23 = __floats2bfloat162_rn(x.z, x.w);
        float2 f01 = __bfloat1622float2(h01);
        float2 f23 = __bfloat1622float2(h23);
        __nv_bfloat162 l01 = __floats2bfloat162_rn(x.x - f01.x, x.y - f01.y);
        __nv_bfloat162 l23 = __floats2bfloat162_rn(x.z - f23.x, x.w - f23.y);
        const uint32_t off = (uint32_t)(row * RS + (c4 << 1));
        *(uint2*)(hi + off) = make_uint2(*(uint32_t*)&h01, *(uint32_t*)&h23);
        *(uint2*)(lo + off) = make_uint2(*(uint32_t*)&l01, *(uint32_t*)&l23);
    }
}

// Core: acc += A[128,K] . B[BROWS,K]^T with 2-term bf16 split (3 MMA products).
// Software-pipelined: chunk c+1 LDG overlaps chunk c MMA.
template<int BROWS, int NT>
__device__ __forceinline__ void mma_core(char* sm, uint32_t smb,
                                         const float* A, int lda,
                                         const float* B, int ldb,
                                         int nchunks, int tid,
                                         float acc[4][NT][4]) {
    const int AH = 0, AL = 128 * RS, BH = 2 * 128 * RS, BL = 2 * 128 * RS + BROWS * RS;
    const int wid = tid >> 5, lane = tid & 31;
    const int wm = wid & 1, wn = wid >> 1;
    const int WN = NT * 8;
    const uint32_t aoff = (uint32_t)((wm * 64 + (lane & 15)) * RS + ((lane >> 4) << 4));
    const uint32_t bi = lane >> 3;
    const uint32_t boff = (uint32_t)((wn * WN + ((bi >> 1) << 3) + (lane & 7)) * RS + ((bi & 1) << 4));

    float4 va[4], vb[(BROWS * 8) / 256];
    ldg_tile<128>(A, lda, tid, va);
    ldg_tile<BROWS>(B, ldb, tid, vb);

    for (int c = 0; c < nchunks; ++c) {
        sts_split<128>(va, sm + AH, sm + AL, tid);
        sts_split<BROWS>(vb, sm + BH, sm + BL, tid);
        __syncthreads();
        if (c + 1 < nchunks) {
            ldg_tile<128>(A + (c + 1) * 32, lda, tid, va);
            ldg_tile<BROWS>(B + (c + 1) * 32, ldb, tid, vb);
        }
#pragma unroll
        for (int s = 0; s < 2; ++s) {
            uint32_t ah[4][4], al[4][4];
            uint32_t bh[(NT + 1) / 2][4], bl[(NT + 1) / 2][4];
            const uint32_t so = s * 32;
#pragma unroll
            for (int mt = 0; mt < 4; ++mt) {
                LDSM4(ah[mt], smb + AH + aoff + mt * 16 * RS + so);
                LDSM4(al[mt], smb + AL + aoff + mt * 16 * RS + so);
            }
#pragma unroll
            for (int p = 0; p < (NT + 1) / 2; ++p) {
                LDSM4(bh[p], smb + BH + boff + p * 16 * RS + so);
                LDSM4(bl[p], smb + BL + boff + p * 16 * RS + so);
            }
#pragma unroll
            for (int mt = 0; mt < 4; ++mt)
#pragma unroll
                for (int nt = 0; nt < NT; ++nt) {
                    const uint32_t b0h = bh[nt >> 1][(nt & 1) * 2];
                    const uint32_t b1h = bh[nt >> 1][(nt & 1) * 2 + 1];
                    const uint32_t b0l = bl[nt >> 1][(nt & 1) * 2];
                    const uint32_t b1l = bl[nt >> 1][(nt & 1) * 2 + 1];
                    MMA(acc[mt][nt], ah[mt], b0h, b1h);   // hi*hi
                    MMA(acc[mt][nt], al[mt], b0h, b1h);   // lo*hi
                    MMA(acc[mt][nt], ah[mt], b0l, b1l);   // hi*lo
                }
        }
        __syncthreads();
    }
}

// ---------------------------------------------------------------------------
// Projection: C[m,n] = A[m,:].W[n,:] + bias[n].
// csel: 0->g_q, 1->g_k, 2->g_vT (transposed), 3->Cp.  Ain==nullptr -> g_a.
// ---------------------------------------------------------------------------
__global__ __launch_bounds__(256, 2) void proj_mma(const float* __restrict__ Ain,
                                                   const float* __restrict__ W,
                                                   const float* __restrict__ bias,
                                                   float* __restrict__ Cp, int csel) {
    __shared__ __align__(16) char sm[40960];
    const uint32_t smb = smem_u32(sm);
    const int tid = threadIdx.x, wid = tid >> 5, lane = tid & 31;
    const int wm = wid & 1, wn = wid >> 1;
    const int bm = blockIdx.y * 128, bn = blockIdx.x * 128;

    const float* A = (Ain ? Ain : g_a) + (size_t)bm * Eq;
    const float* B = W + (size_t)bn * Eq;

    float acc[4][4][4];
#pragma unroll
    for (int a = 0; a < 4; ++a)
#pragma unroll
        for (int b = 0; b < 4; ++b)
#pragma unroll
            for (int c = 0; c < 4; ++c) acc[a][b][c] = 0.f;

    mma_core<128, 4>(sm, smb, A, Eq, B, Eq, 16, tid, acc);
    __syncthreads();

    if (csel != 2) {
        float* C = (csel == 0) ? g_q : (csel == 1) ? g_k : Cp;
#pragma unroll
        for (int mt = 0; mt < 4; ++mt)
#pragma unroll
            for (int nt = 0; nt < 4; ++nt) {
                const int row = bm + wm * 64 + mt * 16 + (lane >> 2);
                const int col = bn + wn * 32 + nt * 8 + ((lane & 3) << 1);
                const float2 bb = *(const float2*)(bias + col);
                float2 o0, o1;
                o0.x = acc[mt][nt][0] + bb.x; o0.y = acc[mt][nt][1] + bb.y;
                o1.x = acc[mt][nt][2] + bb.x; o1.y = acc[mt][nt][3] + bb.y;
                *(float2*)(C + (size_t)row * Eq + col) = o0;
                *(float2*)(C + (size_t)(row + 8) * Eq + col) = o1;
            }
    } else {
        // transpose through smem into g_vT[bh][d][s]
        float (*smt)[65] = (float(*)[65])sm;
#pragma unroll
        for (int hf = 0; hf < 2; ++hf) {
            if ((wn >> 1) == hf) {
#pragma unroll
                for (int mt = 0; mt < 4; ++mt)
#pragma unroll
                    for (int nt = 0; nt < 4; ++nt) {
                        const int row = wm * 64 + mt * 16 + (lane >> 2);
                        const int colL = (wn & 1) * 32 + nt * 8 + ((lane & 3) << 1);
                        const int colG = bn + hf * 64 + colL;
                        const float2 bb = *(const float2*)(bias + colG);
                        smt[row][colL] = acc[mt][nt][0] + bb.x;
                        smt[row][colL + 1] = acc[mt][nt][1] + bb.y;
                        smt[row + 8][colL] = acc[mt][nt][2] + bb.x;
                        smt[row + 8][colL + 1] = acc[mt][nt][3] + bb.y;
                    }
            }
            __syncthreads();
            {
                const int colL = tid & 63, seg = (tid >> 6) << 5;
                const int n = bn + hf * 64 + colL;
                float* dst = g_vT + ((size_t)((bm >> 10) * 8 + (n >> 6)) << 16) +
                             ((size_t)(n & 63) << 10) + (bm & 1023) + seg;
#pragma unroll
                for (int i = 0; i < 8; ++i) {
                    float4 o = make_float4(smt[seg + 4 * i][colL], smt[seg + 4 * i + 1][colL],
                                           smt[seg + 4 * i + 2][colL], smt[seg + 4 * i + 3][colL]);
                    *(float4*)(dst + 4 * i) = o;
                }
            }
            __syncthreads();
        }
    }
}

// ---------------------------------------------------------------------------
// QK^T: S = (1/8) q . k^T per (b,h); causal tile skip. K extent 64 (2 chunks).
// ---------------------------------------------------------------------------
__global__ __launch_bounds__(256, 2) void qk_mma() {
    const int bx = blockIdx.x, by = blockIdx.y;
    if (by < bx) return;
    __shared__ __align__(16) char sm[40960];
    const uint32_t smb = smem_u32(sm);
    const int tid = threadIdx.x, wid = tid >> 5, lane = tid & 31;
    const int wm = wid & 1, wn = wid >> 1;
    const int bh = blockIdx.z, b = bh >> 3, h = bh & 7;
    const int bm = by * 128, bn = bx * 128;

    const float* A = g_q + (size_t)b * Sq * Eq + (size_t)bm * Eq + h * Dq;
    const float* B = g_k + (size_t)b * Sq * Eq + (size_t)bn * Eq + h * Dq;

    float acc[4][4][4];
#pragma unroll
    for (int a = 0; a < 4; ++a)
#pragma unroll
        for (int c = 0; c < 4; ++c)
#pragma unroll
            for (int d = 0; d < 4; ++d) acc[a][c][d] = 0.f;

    mma_core<128, 4>(sm, smb, A, Eq, B, Eq, 2, tid, acc);

    float* S = g_s + ((size_t)bh << 20);
#pragma unroll
    for (int mt = 0; mt < 4; ++mt)
#pragma unroll
        for (int nt = 0; nt < 4; ++nt) {
            const int row = bm + wm * 64 + mt * 16 + (lane >> 2);
            const int col = bn + wn * 32 + nt * 8 + ((lane & 3) << 1);
            float2 o0, o1;
            o0.x = acc[mt][nt][0] * 0.125f; o0.y = acc[mt][nt][1] * 0.125f;
            o1.x = acc[mt][nt][2] * 0.125f; o1.y = acc[mt][nt][3] * 0.125f;
            *(float2*)(S + (size_t)row * Sq + col) = o0;
            *(float2*)(S + (size_t)(row + 8) * Sq + col) = o1;
        }
}

// ---------------------------------------------------------------------------
// PV: out[i,d] = sum_j P[i,j] * VT[d,j].  BN=64, K extent = bm+128 (causal).
// ---------------------------------------------------------------------------
__global__ __launch_bounds__(256, 2) void pv_mma() {
    __shared__ __align__(16) char sm[30720];
    const uint32_t smb = smem_u32(sm);
    const int tid = threadIdx.x, wid = tid >> 5, lane = tid & 31;
    const int wm = wid & 1, wn = wid >> 1;
    const int bh = blockIdx.y, b = bh >> 3, h = bh & 7;
    const int bm = (7 - (int)blockIdx.x) * 128;   // heavy tiles first

    const float* A = g_s + ((size_t)bh << 20) + (size_t)bm * Sq;
    const float* B = g_vT + (size_t)bh * (Dq * Sq);

    float acc[4][2][4];
#pragma unroll
    for (int a = 0; a < 4; ++a)
#pragma unroll
        for (int c = 0; c < 2; ++c)
#pragma unroll
            for (int d = 0; d < 4; ++d) acc[a][c][d] = 0.f;

    mma_core<64, 2>(sm, smb, A, Sq, B, Sq, bm / 32 + 4, tid, acc);

#pragma unroll
    for (int mt = 0; mt < 4; ++mt)
#pragma unroll
        for (int nt = 0; nt < 2; ++nt) {
            const int row = b * Sq + bm + wm * 64 + mt * 16 + (lane >> 2);
            const int col = h * Dq + wn * 16 + nt * 8 + ((lane & 3) << 1);
            float2 o0, o1;
            o0.x = acc[mt][nt][0]; o0.y = acc[mt][nt][1];
            o1.x = acc[mt][nt][2]; o1.y = acc[mt][nt][3];
            *(float2*)(g_a + (size_t)row * Eq + col) = o0;
            *(float2*)(g_a + (size_t)(row + 8) * Eq + col) = o1;
        }
}

// ---------------------------------------------------------------------------
// Softmax + distance-decay + second softmax (row in registers), causal-aware:
// lanes whose 32-wide segment lies fully beyond i skip the load; stores only
// cover j < ceil128(i+1) (exactly what pv_mma reads; rest untouched).
// ---------------------------------------------------------------------------
__device__ __forceinline__ float wmax(float v) {
#pragma unroll
    for (int o = 16; o > 0; o >>= 1) v = fmaxf(v, __shfl_xor_sync(0xffffffffu, v, o));
    return v;
}
__device__ __forceinline__ float wsum(float v) {
#pragma unroll
    for (int o = 16; o > 0; o >>= 1) v += __shfl_xor_sync(0xffffffffu, v, o);
    return v;
}

__global__ __launch_bounds__(256) void softmax_decay(const float* __restrict__ gammas) {
    const int warp = threadIdx.x >> 5;
    const int lane = threadIdx.x & 31;
    const int r = blockIdx.x * 8 + warp;
    const int i = r & (Sq - 1);
    const int h = (r >> 10) & (Hq - 1);
    float* Srow = g_s + (size_t)r * Sq;

    const float gv = gammas[h];
    const float gamma = -(fmaxf(gv, 0.f) + log1pf(__expf(-fabsf(gv))));
    const float NEGINF = -INFINITY;

    const int j0 = lane * 32;
    const bool ld_act = (j0 <= i);
    float s[32];
    if (ld_act) {
#pragma unroll
        for (int t = 0; t < 8; t++) ((float4*)s)[t] = ((const float4*)(Srow + j0))[t];
#pragma unroll
        for (int t = 0; t < 32; t++) if (j0 + t > i) s[t] = NEGINF;
    } else {
#pragma unroll
        for (int t = 0; t < 32; t++) s[t] = NEGINF;
    }

    float m1 = NEGINF;
#pragma unroll
    for (int t = 0; t < 32; t++) m1 = fmaxf(m1, s[t]);
    m1 = wmax(m1);

    float p[32];
    float ls = 0.f;
#pragma unroll
    for (int t = 0; t < 32; t++) { p[t] = __expf(s[t] - m1); ls += p[t]; }
    const float inv1 = 1.f / wsum(ls);

#pragma unroll
    for (int t = 1; t < 32; t++) p[t] += p[t - 1];
    float tot = p[31];
    float x = tot;
#pragma unroll
    for (int off = 1; off < 32; off <<= 1) {
        const float tv = __shfl_up_sync(0xffffffffu, x, off);
        if (lane >= off) x += tv;
    }
    const float excl = x - tot;

    float m2 = NEGINF;
#pragma unroll
    for (int t = 0; t < 32; t++) {
        const int j = j0 + t;
        const float Cj = (excl + p[t]) * inv1;
        const float pd = fmaxf((1.f - Cj) * (float)(i - j), 0.f);
        float eff = __expf(gamma * sqrtf(pd));
        eff = fminf(fmaxf(eff, 1e-5f), 1e5f);
        s[t] *= eff;
        m2 = fmaxf(m2, s[t]);
    }
    m2 = wmax(m2);

    float l2 = 0.f;
#pragma unroll
    for (int t = 0; t < 32; t++) { p[t] = __expf(s[t] - m2); l2 += p[t]; }
    const float scale = ((i == 0) ? 0.f : 1.f) / wsum(l2);
#pragma unroll
    for (int t = 0; t < 32; t++) p[t] *= scale;

    if (j0 < (((i >> 7) + 1) << 7)) {
#pragma unroll
        for (int t = 0; t < 8; t++) ((float4*)(Srow + j0))[t] = ((float4*)p)[t];
    }
}

// ---------------------------------------------------------------------------
extern "C" void kernel_launch(void* const* d_in, const int* in_sizes, int n_in,
                              void* d_out, int out_size) {
    const float* q      = (const float*)d_in[0];
    const float* k      = (const float*)d_in[1];
    const float* v      = (const float*)d_in[2];
    const float* Wk     = (const float*)d_in[3];
    const float* bk     = (const float*)d_in[4];
    const float* Wv     = (const float*)d_in[5];
    const float* bv     = (const float*)d_in[6];
    const float* Wo     = (const float*)d_in[7];
    const float* bo     = (const float*)d_in[8];
    const float* gammas = (const float*)d_in[9];

    dim3 gg(4, 64);
    proj_mma<<<gg, 256>>>(q, Wk, bk, nullptr, 0);                // g_q
    proj_mma<<<gg, 256>>>(k, Wk, bk, nullptr, 1);                // g_k
    proj_mma<<<gg, 256>>>(v, Wv, bv, nullptr, 2);                // g_vT
    qk_mma<<<dim3(8, 8, 64), 256>>>();                           // g_s = scores
    softmax_decay<<<(64 * Sq) / 8, 256>>>(gammas);               // g_s = probs
    pv_mma<<<dim3(8, 64), 256>>>();                              // g_a
    proj_mma<<<gg, 256>>>(nullptr, Wo, bo, (float*)d_out, 3);    // final
}

// round 7
// speedup vs baseline: 3.8743x; 1.0940x over previous
#include <cuda_runtime.h>
#include <cuda_bf16.h>
#include <math.h>
#include <stdint.h>

// Problem constants
#define Bq 8
#define Sq 1024
#define Eq 512
#define Hq 8
#define Dq 64
#define BSq (Bq * Sq)
#define RS 80   // smem row stride bytes: 32 bf16 (64B) + 16B pad (ldmatrix conflict-free)

// ---------------- global scratch (allocation-free) ----------------
__device__ __nv_bfloat16 g_inh[3 * BSq * Eq], g_inl[3 * BSq * Eq];   // q,k,v inputs (split)
__device__ __nv_bfloat16 g_wh[3 * Eq * Eq],  g_wl[3 * Eq * Eq];      // Wk,Wv,Wo (split)
__device__ __nv_bfloat16 g_qh[BSq * Eq], g_ql[BSq * Eq];             // q-proj planes
__device__ __nv_bfloat16 g_kh[BSq * Eq], g_kl[BSq * Eq];             // k-proj planes
__device__ __nv_bfloat16 g_vth[64 * Dq * Sq], g_vtl[64 * Dq * Sq];   // vT planes [bh][d][s]
__device__ __nv_bfloat16 g_ah[BSq * Eq], g_al[BSq * Eq];             // attn-out planes
__device__ __nv_bfloat16 g_ph[(size_t)64 * Sq * Sq], g_pl[(size_t)64 * Sq * Sq]; // P planes
__device__ float g_s[(size_t)64 * Sq * Sq];                          // raw scores fp32

// ---------------- PTX helpers ----------------
__device__ __forceinline__ uint32_t smem_u32(const void* p) {
    uint32_t a;
    asm("{ .reg .u64 t; cvta.to.shared.u64 t, %1; cvt.u32.u64 %0, t; }" : "=r"(a) : "l"(p));
    return a;
}
#define CPA16(sm, g) asm volatile("cp.async.ca.shared.global [%0], [%1], 16;" :: "r"(sm), "l"(g))
#define CPA_COMMIT() asm volatile("cp.async.commit_group;" ::: "memory")

#define LDSM4(r, a) asm volatile( \
    "ldmatrix.sync.aligned.m8n8.x4.shared.b16 {%0,%1,%2,%3}, [%4];" \
    : "=r"((r)[0]), "=r"((r)[1]), "=r"((r)[2]), "=r"((r)[3]) : "r"(a))

#define MMA(d, a, b0, b1) asm volatile( \
    "mma.sync.aligned.m16n8k16.row.col.f32.bf16.bf16.f32 " \
    "{%0,%1,%2,%3}, {%4,%5,%6,%7}, {%8,%9}, {%0,%1,%2,%3};" \
    : "+f"((d)[0]), "+f"((d)[1]), "+f"((d)[2]), "+f"((d)[3]) \
    : "r"((a)[0]), "r"((a)[1]), "r"((a)[2]), "r"((a)[3]), "r"(b0), "r"(b1))

__device__ __forceinline__ void st_split2(__nv_bfloat16* h, __nv_bfloat16* l,
                                          size_t off, float x, float y) {
    __nv_bfloat162 h2 = __floats2bfloat162_rn(x, y);
    float2 f = __bfloat1622float2(h2);
    __nv_bfloat162 l2 = __floats2bfloat162_rn(x - f.x, y - f.y);
    *(__nv_bfloat162*)(h + off) = h2;
    *(__nv_bfloat162*)(l + off) = l2;
}

// ---------------- one-shot fp32 -> bf16 hi/lo split ----------------
__global__ void cvt_all(const float* __restrict__ q, const float* __restrict__ k,
                        const float* __restrict__ v, const float* __restrict__ Wk,
                        const float* __restrict__ Wv, const float* __restrict__ Wo) {
    const int NI = BSq * Eq / 4;   // float4 count per input tensor
    const int NW = Eq * Eq / 4;
    const int total = 3 * NI + 3 * NW;
    for (int idx = blockIdx.x * blockDim.x + threadIdx.x; idx < total;
         idx += gridDim.x * blockDim.x) {
        const float* src; __nv_bfloat16 *h, *l; int off;
        if (idx < NI)                { src = q;  off = idx;               h = g_inh;               l = g_inl; }
        else if (idx < 2 * NI)       { src = k;  off = idx - NI;          h = g_inh + BSq * Eq;     l = g_inl + BSq * Eq; }
        else if (idx < 3 * NI)       { src = v;  off = idx - 2 * NI;      h = g_inh + 2 * BSq * Eq; l = g_inl + 2 * BSq * Eq; }
        else if (idx < 3 * NI + NW)  { src = Wk; off = idx - 3 * NI;      h = g_wh;                l = g_wl; }
        else if (idx < 3 * NI + 2 * NW) { src = Wv; off = idx - 3 * NI - NW; h = g_wh + Eq * Eq;   l = g_wl + Eq * Eq; }
        else                         { src = Wo; off = idx - 3 * NI - 2 * NW; h = g_wh + 2 * Eq * Eq; l = g_wl + 2 * Eq * Eq; }
        float4 x = ((const float4*)src)[off];
        __nv_bfloat162 h01 = __floats2bfloat162_rn(x.x, x.y);
        __nv_bfloat162 h23 = __floats2bfloat162_rn(x.z, x.w);
        float2 f01 = __bfloat1622float2(h01), f23 = __bfloat1622float2(h23);
        __nv_bfloat162 l01 = __floats2bfloat162_rn(x.x - f01.x, x.y - f01.y);
        __nv_bfloat162 l23 = __floats2bfloat162_rn(x.z - f23.x, x.w - f23.y);
        ((__nv_bfloat162*)h)[2 * off] = h01; ((__nv_bfloat162*)h)[2 * off + 1] = h23;
        ((__nv_bfloat162*)l)[2 * off] = l01; ((__nv_bfloat162*)l)[2 * off + 1] = l23;
    }
}

// ---------------- cp.async chunk staging ----------------
template<int BROWS>
__device__ __forceinline__ void issue_chunk(uint32_t smb_buf, int PA, int PB,
    const __nv_bfloat16* __restrict__ Ah, const __nv_bfloat16* __restrict__ Al, int lda,
    const __nv_bfloat16* __restrict__ Bh, const __nv_bfloat16* __restrict__ Bl, int ldb,
    int c, int tid) {
#pragma unroll
    for (int it = 0; it < 2; ++it) {                 // A: 128 rows x 4 16B-units
        const int u = tid + it * 256;
        const int row = u >> 2, q16 = u & 3;
        const uint32_t so = smb_buf + row * RS + q16 * 16;
        const size_t go = (size_t)row * lda + c * 32 + q16 * 8;
        CPA16(so, Ah + go);
        CPA16(so + PA, Al + go);
    }
#pragma unroll
    for (int it = 0; it < (BROWS * 4) / 256; ++it) { // B: BROWS rows x 4 units
        const int u = tid + it * 256;
        const int row = u >> 2, q16 = u & 3;
        const uint32_t so = smb_buf + 2 * PA + row * RS + q16 * 16;
        const size_t go = (size_t)row * ldb + c * 32 + q16 * 8;
        CPA16(so, Bh + go);
        CPA16(so + PB, Bl + go);
    }
    CPA_COMMIT();
}

// Core: acc += A[128,K] . B[BROWS,K]^T, 2-term bf16 split (hh + lh + hl).
// cp.async double-buffered; no conversion in the loop.
template<int BROWS, int NT>
__device__ __forceinline__ void mma_core(uint32_t smb,
    const __nv_bfloat16* Ah, const __nv_bfloat16* Al, int lda,
    const __nv_bfloat16* Bh, const __nv_bfloat16* Bl, int ldb,
    int nchunks, int tid, float acc[4][NT][4]) {
    const int PA = 128 * RS, PB = BROWS * RS, BUF = 2 * PA + 2 * PB;
    const int wid = tid >> 5, lane = tid & 31;
    const int wm = wid & 1, wn = wid >> 1;
    const uint32_t aoff = (uint32_t)((wm * 64 + (lane & 15)) * RS + ((lane >> 4) << 4));
    const uint32_t bi = lane >> 3;
    const uint32_t boff = (uint32_t)((wn * (NT * 8) + ((bi >> 1) << 3) + (lane & 7)) * RS +
                                     ((bi & 1) << 4));

    issue_chunk<BROWS>(smb, PA, PB, Ah, Al, lda, Bh, Bl, ldb, 0, tid);
    for (int c = 0; c < nchunks; ++c) {
        if (c + 1 < nchunks) {
            issue_chunk<BROWS>(smb + ((c + 1) & 1) * BUF, PA, PB, Ah, Al, lda, Bh, Bl, ldb,
                               c + 1, tid);
            asm volatile("cp.async.wait_group 1;" ::: "memory");
        } else {
            asm volatile("cp.async.wait_group 0;" ::: "memory");
        }
        __syncthreads();
        const uint32_t AHb = smb + (c & 1) * BUF, ALb = AHb + PA;
        const uint32_t BHb = AHb + 2 * PA, BLb = BHb + PB;
#pragma unroll
        for (int s = 0; s < 2; ++s) {
            uint32_t ah[4][4], al[4][4];
            uint32_t bh[(NT + 1) / 2][4], bl[(NT + 1) / 2][4];
            const uint32_t so = s * 32;
#pragma unroll
            for (int mt = 0; mt < 4; ++mt) {
                LDSM4(ah[mt], AHb + aoff + mt * 16 * RS + so);
                LDSM4(al[mt], ALb + aoff + mt * 16 * RS + so);
            }
#pragma unroll
            for (int p = 0; p < (NT + 1) / 2; ++p) {
                LDSM4(bh[p], BHb + boff + p * 16 * RS + so);
                LDSM4(bl[p], BLb + boff + p * 16 * RS + so);
            }
#pragma unroll
            for (int mt = 0; mt < 4; ++mt)
#pragma unroll
                for (int nt = 0; nt < NT; ++nt) {
                    const uint32_t b0h = bh[nt >> 1][(nt & 1) * 2];
                    const uint32_t b1h = bh[nt >> 1][(nt & 1) * 2 + 1];
                    const uint32_t b0l = bl[nt >> 1][(nt & 1) * 2];
                    const uint32_t b1l = bl[nt >> 1][(nt & 1) * 2 + 1];
                    MMA(acc[mt][nt], ah[mt], b0h, b1h);   // hi*hi
                    MMA(acc[mt][nt], al[mt], b0h, b1h);   // lo*hi
                    MMA(acc[mt][nt], ah[mt], b0l, b1l);   // hi*lo
                }
        }
        __syncthreads();
    }
}

// ---------------------------------------------------------------------------
// Projection: C[m,n] = A[m,:].W[n,:] + bias[n].
// asel: 0=q,1=k,2=v inputs, 3=attn-out planes. bsel: 0=Wk,1=Wv,2=Wo.
// csel: 0->g_q planes, 1->g_k planes, 2->g_vT planes, 3->fp32 Cp.
// ---------------------------------------------------------------------------
__global__ __launch_bounds__(256, 2) void proj_mma(int asel, int bsel,
                                                   const float* __restrict__ bias,
                                                   float* __restrict__ Cp, int csel) {
    extern __shared__ __align__(16) char sm[];
    const uint32_t smb = smem_u32(sm);
    const int tid = threadIdx.x, wid = tid >> 5, lane = tid & 31;
    const int wm = wid & 1, wn = wid >> 1;
    const int bm = blockIdx.y * 128, bn = blockIdx.x * 128;

    const __nv_bfloat16* Ah = ((asel < 3) ? g_inh + (size_t)asel * BSq * Eq : g_ah) + (size_t)bm * Eq;
    const __nv_bfloat16* Al = ((asel < 3) ? g_inl + (size_t)asel * BSq * Eq : g_al) + (size_t)bm * Eq;
    const __nv_bfloat16* Bh = g_wh + (size_t)bsel * Eq * Eq + (size_t)bn * Eq;
    const __nv_bfloat16* Bl = g_wl + (size_t)bsel * Eq * Eq + (size_t)bn * Eq;

    float acc[4][4][4];
#pragma unroll
    for (int a = 0; a < 4; ++a)
#pragma unroll
        for (int b = 0; b < 4; ++b)
#pragma unroll
            for (int c = 0; c < 4; ++c) acc[a][b][c] = 0.f;

    mma_core<128, 4>(smb, Ah, Al, Eq, Bh, Bl, Eq, 16, tid, acc);
    __syncthreads();

    if (csel == 3) {
#pragma unroll
        for (int mt = 0; mt < 4; ++mt)
#pragma unroll
            for (int nt = 0; nt < 4; ++nt) {
                const int row = bm + wm * 64 + mt * 16 + (lane >> 2);
                const int col = bn + wn * 32 + nt * 8 + ((lane & 3) << 1);
                const float2 bb = *(const float2*)(bias + col);
                float2 o0, o1;
                o0.x = acc[mt][nt][0] + bb.x; o0.y = acc[mt][nt][1] + bb.y;
                o1.x = acc[mt][nt][2] + bb.x; o1.y = acc[mt][nt][3] + bb.y;
                *(float2*)(Cp + (size_t)row * Eq + col) = o0;
                *(float2*)(Cp + (size_t)(row + 8) * Eq + col) = o1;
            }
    } else if (csel != 2) {
        __nv_bfloat16* Ch = (csel == 0) ? g_qh : g_kh;
        __nv_bfloat16* Cl = (csel == 0) ? g_ql : g_kl;
#pragma unroll
        for (int mt = 0; mt < 4; ++mt)
#pragma unroll
            for (int nt = 0; nt < 4; ++nt) {
                const int row = bm + wm * 64 + mt * 16 + (lane >> 2);
                const int col = bn + wn * 32 + nt * 8 + ((lane & 3) << 1);
                const float2 bb = *(const float2*)(bias + col);
                st_split2(Ch, Cl, (size_t)row * Eq + col,
                          acc[mt][nt][0] + bb.x, acc[mt][nt][1] + bb.y);
                st_split2(Ch, Cl, (size_t)(row + 8) * Eq + col,
                          acc[mt][nt][2] + bb.x, acc[mt][nt][3] + bb.y);
            }
    } else {
        // transpose through smem into g_vT planes [bh][d][s]
        float (*smt)[65] = (float(*)[65])sm;
#pragma unroll
        for (int hf = 0; hf < 2; ++hf) {
            if ((wn >> 1) == hf) {
#pragma unroll
                for (int mt = 0; mt < 4; ++mt)
#pragma unroll
                    for (int nt = 0; nt < 4; ++nt) {
                        const int row = wm * 64 + mt * 16 + (lane >> 2);
                        const int colL = (wn & 1) * 32 + nt * 8 + ((lane & 3) << 1);
                        const int colG = bn + hf * 64 + colL;
                        const float2 bb = *(const float2*)(bias + colG);
                        smt[row][colL] = acc[mt][nt][0] + bb.x;
                        smt[row][colL + 1] = acc[mt][nt][1] + bb.y;
                        smt[row + 8][colL] = acc[mt][nt][2] + bb.x;
                        smt[row + 8][colL + 1] = acc[mt][nt][3] + bb.y;
                    }
            }
            __syncthreads();
            {
                const int colL = tid & 63, seg = (tid >> 6) << 5;
                const int n = bn + hf * 64 + colL;
                const size_t dbase = ((size_t)((bm >> 10) * 8 + (n >> 6)) << 16) +
                                     ((size_t)(n & 63) << 10) + (bm & 1023) + seg;
#pragma unroll
                for (int i = 0; i < 8; ++i) {
                    const float a0 = smt[seg + 4 * i][colL], a1 = smt[seg + 4 * i + 1][colL];
                    const float a2 = smt[seg + 4 * i + 2][colL], a3 = smt[seg + 4 * i + 3][colL];
                    st_split2(g_vth, g_vtl, dbase + 4 * i, a0, a1);
                    st_split2(g_vth, g_vtl, dbase + 4 * i + 2, a2, a3);
                }
            }
            __syncthreads();
        }
    }
}

// ---------------------------------------------------------------------------
// QK^T: S = (1/8) q . k^T per (b,h); causal tile skip. K=64 (2 chunks).
// ---------------------------------------------------------------------------
__global__ __launch_bounds__(256, 2) void qk_mma() {
    const int bx = blockIdx.x, by = blockIdx.y;
    if (by < bx) return;
    extern __shared__ __align__(16) char sm[];
    const uint32_t smb = smem_u32(sm);
    const int tid = threadIdx.x, wid = tid >> 5, lane = tid & 31;
    const int wm = wid & 1, wn = wid >> 1;
    const int bh = blockIdx.z, b = bh >> 3, h = bh & 7;
    const int bm = by * 128, bn = bx * 128;

    const size_t abase = (size_t)(b * Sq + bm) * Eq + h * Dq;
    const size_t bbase = (size_t)(b * Sq + bn) * Eq + h * Dq;

    float acc[4][4][4];
#pragma unroll
    for (int a = 0; a < 4; ++a)
#pragma unroll
        for (int c = 0; c < 4; ++c)
#pragma unroll
            for (int d = 0; d < 4; ++d) acc[a][c][d] = 0.f;

    mma_core<128, 4>(smb, g_qh + abase, g_ql + abase, Eq,
                     g_kh + bbase, g_kl + bbase, Eq, 2, tid, acc);

    float* S = g_s + ((size_t)bh << 20);
#pragma unroll
    for (int mt = 0; mt < 4; ++mt)
#pragma unroll
        for (int nt = 0; nt < 4; ++nt) {
            const int row = bm + wm * 64 + mt * 16 + (lane >> 2);
            const int col = bn + wn * 32 + nt * 8 + ((lane & 3) << 1);
            float2 o0, o1;
            o0.x = acc[mt][nt][0] * 0.125f; o0.y = acc[mt][nt][1] * 0.125f;
            o1.x = acc[mt][nt][2] * 0.125f; o1.y = acc[mt][nt][3] * 0.125f;
            *(float2*)(S + (size_t)row * Sq + col) = o0;
            *(float2*)(S + (size_t)(row + 8) * Sq + col) = o1;
        }
}

// ---------------------------------------------------------------------------
// PV: out[i,d] = sum_j P[i,j] * VT[d,j].  BN=64, K extent = bm+128 (causal).
// ---------------------------------------------------------------------------
__global__ __launch_bounds__(256, 2) void pv_mma() {
    extern __shared__ __align__(16) char sm[];
    const uint32_t smb = smem_u32(sm);
    const int tid = threadIdx.x, wid = tid >> 5, lane = tid & 31;
    const int wm = wid & 1, wn = wid >> 1;
    const int bh = blockIdx.y, b = bh >> 3, h = bh & 7;
    const int bm = (7 - (int)blockIdx.x) * 128;   // heavy tiles first

    const size_t pbase = ((size_t)bh << 20) + (size_t)bm * Sq;
    const size_t vbase = (size_t)bh * (Dq * Sq);

    float acc[4][2][4];
#pragma unroll
    for (int a = 0; a < 4; ++a)
#pragma unroll
        for (int c = 0; c < 2; ++c)
#pragma unroll
            for (int d = 0; d < 4; ++d) acc[a][c][d] = 0.f;

    mma_core<64, 2>(smb, g_ph + pbase, g_pl + pbase, Sq,
                    g_vth + vbase, g_vtl + vbase, Sq, bm / 32 + 4, tid, acc);

#pragma unroll
    for (int mt = 0; mt < 4; ++mt)
#pragma unroll
        for (int nt = 0; nt < 2; ++nt) {
            const int row = b * Sq + bm + wm * 64 + mt * 16 + (lane >> 2);
            const int col = h * Dq + wn * 16 + nt * 8 + ((lane & 3) << 1);
            st_split2(g_ah, g_al, (size_t)row * Eq + col, acc[mt][nt][0], acc[mt][nt][1]);
            st_split2(g_ah, g_al, (size_t)(row + 8) * Eq + col, acc[mt][nt][2], acc[mt][nt][3]);
        }
}

// ---------------------------------------------------------------------------
// Softmax + distance-decay + second softmax; causal-aware; writes P planes.
// ---------------------------------------------------------------------------
__device__ __forceinline__ float wmax(float v) {
#pragma unroll
    for (int o = 16; o > 0; o >>= 1) v = fmaxf(v, __shfl_xor_sync(0xffffffffu, v, o));
    return v;
}
__device__ __forceinline__ float wsum(float v) {
#pragma unroll
    for (int o = 16; o > 0; o >>= 1) v += __shfl_xor_sync(0xffffffffu, v, o);
    return v;
}

__global__ __launch_bounds__(256) void softmax_decay(const float* __restrict__ gammas) {
    const int warp = threadIdx.x >> 5;
    const int lane = threadIdx.x & 31;
    const int r = blockIdx.x * 8 + warp;
    const int i = r & (Sq - 1);
    const int h = (r >> 10) & (Hq - 1);
    const float* Srow = g_s + (size_t)r * Sq;

    const float gv = gammas[h];
    const float gamma = -(fmaxf(gv, 0.f) + log1pf(__expf(-fabsf(gv))));
    const float NEGINF = -INFINITY;

    const int j0 = lane * 32;
    float s[32];
    if (j0 <= i) {
#pragma unroll
        for (int t = 0; t < 8; t++) ((float4*)s)[t] = ((const float4*)(Srow + j0))[t];
#pragma unroll
        for (int t = 0; t < 32; t++) if (j0 + t > i) s[t] = NEGINF;
    } else {
#pragma unroll
        for (int t = 0; t < 32; t++) s[t] = NEGINF;
    }

    float m1 = NEGINF;
#pragma unroll
    for (int t = 0; t < 32; t++) m1 = fmaxf(m1, s[t]);
    m1 = wmax(m1);

    float p[32];
    float ls = 0.f;
#pragma unroll
    for (int t = 0; t < 32; t++) { p[t] = __expf(s[t] - m1); ls += p[t]; }
    const float inv1 = 1.f / wsum(ls);

#pragma unroll
    for (int t = 1; t < 32; t++) p[t] += p[t - 1];
    float tot = p[31];
    float x = tot;
#pragma unroll
    for (int off = 1; off < 32; off <<= 1) {
        const float tv = __shfl_up_sync(0xffffffffu, x, off);
        if (lane >= off) x += tv;
    }
    const float excl = x - tot;

    float m2 = NEGINF;
#pragma unroll
    for (int t = 0; t < 32; t++) {
        const int j = j0 + t;
        const float Cj = (excl + p[t]) * inv1;
        const float pd = fmaxf((1.f - Cj) * (float)(i - j), 0.f);
        float eff = __expf(gamma * sqrtf(pd));
        eff = fminf(fmaxf(eff, 1e-5f), 1e5f);
        s[t] *= eff;
        m2 = fmaxf(m2, s[t]);
    }
    m2 = wmax(m2);

    float l2 = 0.f;
#pragma unroll
    for (int t = 0; t < 32; t++) { p[t] = __expf(s[t] - m2); l2 += p[t]; }
    const float scale = ((i == 0) ? 0.f : 1.f) / wsum(l2);
#pragma unroll
    for (int t = 0; t < 32; t++) p[t] *= scale;

    if (j0 < (((i >> 7) + 1) << 7)) {   // pv reads only up to the row's diagonal tile
        uint32_t hw[16], lw[16];
#pragma unroll
        for (int t = 0; t < 32; t += 2) {
            __nv_bfloat162 h2 = __floats2bfloat162_rn(p[t], p[t + 1]);
            float2 f = __bfloat1622float2(h2);
            __nv_bfloat162 l2v = __floats2bfloat162_rn(p[t] - f.x, p[t + 1] - f.y);
            hw[t >> 1] = *(uint32_t*)&h2;
            lw[t >> 1] = *(uint32_t*)&l2v;
        }
        uint4* dh = (uint4*)(g_ph + (size_t)r * Sq + j0);
        uint4* dl = (uint4*)(g_pl + (size_t)r * Sq + j0);
#pragma unroll
        for (int w = 0; w < 4; ++w) { dh[w] = ((uint4*)hw)[w]; dl[w] = ((uint4*)lw)[w]; }
    }
}

// ---------------------------------------------------------------------------
extern "C" void kernel_launch(void* const* d_in, const int* in_sizes, int n_in,
                              void* d_out, int out_size) {
    const float* q      = (const float*)d_in[0];
    const float* k      = (const float*)d_in[1];
    const float* v      = (const float*)d_in[2];
    const float* bk     = (const float*)d_in[4];
    const float* bv     = (const float*)d_in[6];
    const float* bo     = (const float*)d_in[8];
    const float* gammas = (const float*)d_in[9];
    const float* Wk     = (const float*)d_in[3];
    const float* Wv     = (const float*)d_in[5];
    const float* Wo     = (const float*)d_in[7];

    const int SM_PROJ = 2 * (2 * 128 * RS + 2 * 128 * RS);  // 81920
    const int SM_PV   = 2 * (2 * 128 * RS + 2 * 64 * RS);   // 61440
    cudaFuncSetAttribute(proj_mma, cudaFuncAttributeMaxDynamicSharedMemorySize, SM_PROJ);
    cudaFuncSetAttribute(qk_mma,   cudaFuncAttributeMaxDynamicSharedMemorySize, SM_PROJ);
    cudaFuncSetAttribute(pv_mma,   cudaFuncAttributeMaxDynamicSharedMemorySize, SM_PV);

    dim3 gg(4, 64);
    cvt_all<<<1024, 256>>>(q, k, v, Wk, Wv, Wo);
    proj_mma<<<gg, 256, SM_PROJ>>>(0, 0, bk, nullptr, 0);            // q -> g_q planes
    proj_mma<<<gg, 256, SM_PROJ>>>(1, 0, bk, nullptr, 1);            // k -> g_k planes
    proj_mma<<<gg, 256, SM_PROJ>>>(2, 1, bv, nullptr, 2);            // v -> g_vT planes
    qk_mma<<<dim3(8, 8, 64), 256, SM_PROJ>>>();                      // g_s = scores
    softmax_decay<<<(64 * Sq) / 8, 256>>>(gammas);                   // P planes
    pv_mma<<<dim3(8, 64), 256, SM_PV>>>();                           // g_a planes
    proj_mma<<<gg, 256, SM_PROJ>>>(3, 2, bo, (float*)d_out, 3);      // final fp32
}